// round 6
// baseline (speedup 1.0000x reference)
#include <cuda_runtime.h>
#include <cstdint>

#define K1      100
#define H       256
#define ROWS    80      // rows per block (500000 = 6250 * 80)
#define RPAD    84      // act k-row stride (floats, 16B aligned)
#define KBS     16      // k-chunk
#define THREADS 640     // 20 warps: (row-group 0..9) x (col-half 0..1)
#define HDS     (2*ROWS)   // h-dup slab stride per k (160 floats)

#define ACT_F   (H * RPAD)
#define WSLAB_F (KBS * H)
#define HSLAB_F (KBS * HDS)
#define SMEM_FLOATS (2*ACT_F + 2*WSLAB_F + 2*HSLAB_F + H)
#define SMEM_BYTES  (SMEM_FLOATS * 4)   // 226,304 B

typedef unsigned long long ull;

__device__ __forceinline__ ull pack2(float lo, float hi) {
    ull r; asm("mov.b64 %0, {%1,%2};" : "=l"(r) : "f"(lo), "f"(hi)); return r;
}
__device__ __forceinline__ void unpack2(ull v, float& lo, float& hi) {
    asm("mov.b64 {%0,%1}, %2;" : "=f"(lo), "=f"(hi) : "l"(v));
}
__device__ __forceinline__ void fma2(ull& d, ull a, ull b) {
    asm("fma.rn.f32x2 %0, %1, %2, %0;" : "+l"(d) : "l"(a), "l"(b));
}

// ---- W chunk staging (registers; LDG issued early, STS after compute) ----
__device__ __forceinline__ void stage_ld_w(float4 st[2], const float* __restrict__ Wg,
                                           int kb, int kc) {
    const float4* src = (const float4*)(Wg + (size_t)kb * H);
    int n = kc * (H / 4);
#pragma unroll
    for (int i = 0; i < 2; i++) {
        int idx = threadIdx.x + i * THREADS;
        if (idx < n) st[i] = src[idx];
    }
}
__device__ __forceinline__ void stage_st_w(const float4 st[2], float* buf, int kc) {
    float4* dst = (float4*)buf;
    int n = kc * (H / 4);
#pragma unroll
    for (int i = 0; i < 2; i++) {
        int idx = threadIdx.x + i * THREADS;
        if (idx < n) dst[idx] = st[i];
    }
}
// ---- h-dup staging: read float2 from act_in (smem), write duplicated float4 ----
__device__ __forceinline__ float2 stage_ld_h(const float* act_in, int kb, int kc) {
    float2 hv = make_float2(0.f, 0.f);
    int tid = threadIdx.x;
    if (tid < kc * (ROWS / 2)) {
        int k  = tid / (ROWS / 2);
        int rp = tid - k * (ROWS / 2);
        hv = *(const float2*)(act_in + (size_t)(kb + k) * RPAD + 2 * rp);
    }
    return hv;
}
__device__ __forceinline__ void stage_st_h(float2 hv, float* hsl, int kc) {
    int tid = threadIdx.x;
    if (tid < kc * (ROWS / 2)) {
        int k  = tid / (ROWS / 2);
        int rp = tid - k * (ROWS / 2);
        *(float4*)(hsl + k * HDS + rp * 4) = make_float4(hv.x, hv.x, hv.y, hv.y);
    }
}

// ---- inner compute over one k-chunk ----
// Lane owns 4 cols (one ulonglong2 of W); warp owns 8 rows (4 dup-pairs, broadcast).
template<int KC>
__device__ __forceinline__ void comp_chunk(ull acc[16], const float* hb, const float* wp) {
#pragma unroll
    for (int k = 0; k < KC; k++) {
        const ulonglong2* hp = (const ulonglong2*)(hb + (size_t)k * HDS);
        ulonglong2 h01 = hp[0];  // dup(r0),   dup(r0+1)
        ulonglong2 h23 = hp[1];
        ulonglong2 h45 = hp[2];
        ulonglong2 h67 = hp[3];
        ulonglong2 w   = *(const ulonglong2*)(wp + (size_t)k * H);
        fma2(acc[0],  h01.x, w.x); fma2(acc[1],  h01.x, w.y);
        fma2(acc[2],  h01.y, w.x); fma2(acc[3],  h01.y, w.y);
        fma2(acc[4],  h23.x, w.x); fma2(acc[5],  h23.x, w.y);
        fma2(acc[6],  h23.y, w.x); fma2(acc[7],  h23.y, w.y);
        fma2(acc[8],  h45.x, w.x); fma2(acc[9],  h45.x, w.y);
        fma2(acc[10], h45.y, w.x); fma2(acc[11], h45.y, w.y);
        fma2(acc[12], h67.x, w.x); fma2(acc[13], h67.x, w.y);
        fma2(acc[14], h67.y, w.x); fma2(acc[15], h67.y, w.y);
    }
}

// One layer: act_out[j][r] = tanh( sum_k act_in[k][r] * W[k][j] + b[j] )
__device__ __forceinline__ void mlp_layer(
    const float* __restrict__ Wg, const float* __restrict__ bg,
    const float* act_in, float* act_out,
    float* wsl0, float* wsl1, float* hsl0, float* hsl1, int Kdim)
{
    int lane = threadIdx.x & 31, warp = threadIdx.x >> 5;
    int rg = warp % 10, ch = warp / 10;
    int r0 = rg * 8;                 // warp's 8 rows
    int c0 = ch * 128 + lane * 4;    // lane's 4 cols

    ull acc[16];
#pragma unroll
    for (int cp = 0; cp < 2; cp++) {
        float2 b2 = *(const float2*)(bg + c0 + 2 * cp);
        ull bp = pack2(b2.x, b2.y);
#pragma unroll
        for (int r = 0; r < 8; r++) acc[r * 2 + cp] = bp;
    }

    int nch = (Kdim + KBS - 1) / KBS;
    int kc0 = (Kdim < KBS) ? Kdim : KBS;
    float4 stw[2];
    float2 sth;

    stage_ld_w(stw, Wg, 0, kc0);     // global read: race-free before barrier
    __syncthreads();                 // act_in fully written; prior slab readers done
    sth = stage_ld_h(act_in, 0, kc0);  // smem read AFTER barrier (round-5 bug fixed)

    for (int c = 0; c < nch; c++) {
        float* wbuf = (c & 1) ? wsl1 : wsl0;
        float* hbuf = (c & 1) ? hsl1 : hsl0;
        int kc = Kdim - c * KBS; if (kc > KBS) kc = KBS;
        stage_st_w(stw, wbuf, kc);
        stage_st_h(sth, hbuf, kc);
        __syncthreads();                          // slab c visible; other buffer free
        if (c + 1 < nch) {
            int kcn = Kdim - (c + 1) * KBS; if (kcn > KBS) kcn = KBS;
            stage_ld_w(stw, Wg, (c + 1) * KBS, kcn);     // lands during compute
            sth = stage_ld_h(act_in, (c + 1) * KBS, kcn); // act_in stable all layer
        }
        const float* hb = hbuf + r0 * 2;
        const float* wp = wbuf + c0;
        if (kc == KBS) comp_chunk<KBS>(acc, hb, wp);
        else           comp_chunk<4>(acc, hb, wp);   // K1 tail: 100-96=4 exactly
    }

    // tanh + transposed store [j][r]
#pragma unroll
    for (int cp = 0; cp < 2; cp++) {
#pragma unroll
        for (int jj = 0; jj < 2; jj++) {
            float v[8];
#pragma unroll
            for (int r = 0; r < 8; r++) {
                float a, b; unpack2(acc[r * 2 + cp], a, b);
                v[r] = tanhf(jj ? b : a);
            }
            float* dst = act_out + (size_t)(c0 + 2 * cp + jj) * RPAD + r0;
            *(float4*)dst       = make_float4(v[0], v[1], v[2], v[3]);
            *(float4*)(dst + 4) = make_float4(v[4], v[5], v[6], v[7]);
        }
    }
}

__global__ void __launch_bounds__(THREADS, 1)
gnn_mlp_kernel(const float* __restrict__ ea,
               const float* __restrict__ W1, const float* __restrict__ b1,
               const float* __restrict__ W2, const float* __restrict__ b2,
               const float* __restrict__ W3, const float* __restrict__ b3,
               const float* __restrict__ W4, const float* __restrict__ b4,
               float* __restrict__ out, int ntot)
{
    extern __shared__ float smem[];
    float* actA = smem;
    float* actB = actA + ACT_F;
    float* wsl0 = actB + ACT_F;
    float* wsl1 = wsl0 + WSLAB_F;
    float* hsl0 = wsl1 + WSLAB_F;
    float* hsl1 = hsl0 + HSLAB_F;
    float* w4s  = hsl1 + HSLAB_F;

    int row0 = blockIdx.x * ROWS;
    int tid  = threadIdx.x;

    // e-tile (ROWS x K1) -> actB transposed [k][r]
    for (int idx = tid; idx < ROWS * K1; idx += THREADS) {
        int r = idx / K1;
        int k = idx - r * K1;
        int row = row0 + r;
        actB[k * RPAD + r] = (row < ntot) ? ea[(size_t)row * K1 + k] : 0.0f;
    }
    if (tid < H) w4s[tid] = W4[tid];

    mlp_layer(W1, b1, actB, actA, wsl0, wsl1, hsl0, hsl1, K1);  // e    -> actA
    mlp_layer(W2, b2, actA, actB, wsl0, wsl1, hsl0, hsl1, H);   // actA -> actB
    mlp_layer(W3, b3, actB, actA, wsl0, wsl1, hsl0, hsl1, H);   // actB -> actA

    __syncthreads();   // layer-3 epilogue stores visible

    // Layer 4: 8 threads per row, shuffle reduce
    {
        int r   = tid >> 3;        // 0..79
        int seg = tid & 7;         // 32-k segment
        const float* hcol = actA + r;
        float s = 0.f;
        int kb = seg * 32;
#pragma unroll 8
        for (int i = 0; i < 32; i++) {
            s += hcol[(kb + i) * RPAD] * w4s[kb + i];
        }
        s += __shfl_down_sync(0xffffffff, s, 4);
        s += __shfl_down_sync(0xffffffff, s, 2);
        s += __shfl_down_sync(0xffffffff, s, 1);
        if (seg == 0) {
            float z = s + b4[0];
            int row = row0 + r;
            if (row < ntot) out[row] = 1.0f / (1.0f + expf(-z));
        }
    }
}

extern "C" void kernel_launch(void* const* d_in, const int* in_sizes, int n_in,
                              void* d_out, int out_size)
{
    // Inputs: x, edge_index, edge_attr, W1, b1, W2, b2, W3, b3, W4, b4
    const float* ea = (const float*)d_in[2];
    const float* W1 = (const float*)d_in[3];
    const float* b1 = (const float*)d_in[4];
    const float* W2 = (const float*)d_in[5];
    const float* b2 = (const float*)d_in[6];
    const float* W3 = (const float*)d_in[7];
    const float* b3 = (const float*)d_in[8];
    const float* W4 = (const float*)d_in[9];
    const float* b4 = (const float*)d_in[10];
    float* out = (float*)d_out;

    int ntot = out_size;                  // 500000
    int grid = (ntot + ROWS - 1) / ROWS;  // 6250

    cudaFuncSetAttribute(gnn_mlp_kernel,
                         cudaFuncAttributeMaxDynamicSharedMemorySize, SMEM_BYTES);
    gnn_mlp_kernel<<<grid, THREADS, SMEM_BYTES>>>(ea, W1, b1, W2, b2, W3, b3,
                                                  W4, b4, out, ntot);
}

// round 8
// speedup vs baseline: 3.2376x; 3.2376x over previous
#include <cuda_runtime.h>
#include <cuda_bf16.h>
#include <cstdint>

#define K1REAL  100
#define HDIM    256
#define TILE_M  128
#define THREADS 512          // 16 warps: warpm=wid&3 (m32), warpn=wid>>2 (n64)
#define KCH     32           // k-chunk
#define NCHUNK  20           // L1:4 (k padded to 128), L2:8, L3:8

// act: bf16 [128][264] per image (row 528B = 33 quads -> ldmatrix conflict-free)
#define ACT_STRIDE_B 528
#define ACT_IMG_B    (TILE_M * ACT_STRIDE_B)          // 67,584
// weight chunk image: [256 n][40 bf16] (k32 + pad8; row 80B = 5 quads, conflict-free)
#define WROW_B   80
#define WIMG_B   (HDIM * WROW_B)                      // 20,480
#define WCHUNK_B (2 * WIMG_B)                         // 40,960 (hi, lo)

#define SM_ACT_HI 0
#define SM_ACT_LO ACT_IMG_B
#define SM_WBUF   (2 * ACT_IMG_B)                     // 2 chunk buffers
#define SM_BIAS   (SM_WBUF + 2 * WCHUNK_B)            // 3 * 256 floats
#define SM_W4     (SM_BIAS + 3072)
#define SMEM_TOTAL (SM_W4 + 1024)                     // 221,184 B

// pre-split weights: [chunk][img][n][40] bf16
__device__ __nv_bfloat16 WCH[(size_t)NCHUNK * 2 * HDIM * (WROW_B / 2)];

__device__ __forceinline__ uint32_t smem_u32(const void* p) {
    uint32_t a;
    asm("{ .reg .u64 t; cvta.to.shared.u64 t, %1; cvt.u32.u64 %0, t; }" : "=r"(a) : "l"(p));
    return a;
}
__device__ __forceinline__ void ldsm_x4(uint32_t r[4], uint32_t addr) {
    asm volatile("ldmatrix.sync.aligned.m8n8.x4.shared.b16 {%0,%1,%2,%3}, [%4];"
                 : "=r"(r[0]), "=r"(r[1]), "=r"(r[2]), "=r"(r[3]) : "r"(addr));
}
__device__ __forceinline__ void mma_bf16(float d[4], const uint32_t a[4],
                                         uint32_t b0, uint32_t b1) {
    asm volatile(
        "mma.sync.aligned.m16n8k16.row.col.f32.bf16.bf16.f32 "
        "{%0,%1,%2,%3}, {%4,%5,%6,%7}, {%8,%9}, {%0,%1,%2,%3};"
        : "+f"(d[0]), "+f"(d[1]), "+f"(d[2]), "+f"(d[3])
        : "r"(a[0]), "r"(a[1]), "r"(a[2]), "r"(a[3]), "r"(b0), "r"(b1));
}
__device__ __forceinline__ float tanh_fast(float x) {
    float y; asm("tanh.approx.f32 %0, %1;" : "=f"(y) : "f"(x)); return y;
}
__device__ __forceinline__ uint32_t pack_bf2(float a, float b) {
    __nv_bfloat162 t;
    t.x = __float2bfloat16(a); t.y = __float2bfloat16(b);
    return *reinterpret_cast<uint32_t*>(&t);
}

// ---------------- weight pre-split: W[k][n] -> WCH[chunk][img][n][k32pad] ------
__global__ void wsplit_kernel(const float* __restrict__ W1,
                              const float* __restrict__ W2,
                              const float* __restrict__ W3) {
    int n = threadIdx.x;
    int kidx = blockIdx.x;                 // 0..639 padded-k
    const float* W; int kk, Kreal, chunk;
    if (kidx < 128)      { kk = kidx;       W = W1; Kreal = K1REAL; chunk = 0  + (kk >> 5); }
    else if (kidx < 384) { kk = kidx - 128; W = W2; Kreal = HDIM;   chunk = 4  + (kk >> 5); }
    else                 { kk = kidx - 384; W = W3; Kreal = HDIM;   chunk = 12 + (kk >> 5); }
    float w = (kk < Kreal) ? W[kk * HDIM + n] : 0.0f;
    __nv_bfloat16 hi = __float2bfloat16(w);
    __nv_bfloat16 lo = __float2bfloat16(w - __bfloat162float(hi));
    size_t base = ((size_t)(chunk * 2) * HDIM + n) * 40 + (kk & 31);
    WCH[base]             = hi;
    WCH[base + HDIM * 40] = lo;
}

// ---------------- main kernel ----------------
__global__ void __launch_bounds__(THREADS, 1)
gnn_mma_kernel(const float* __restrict__ ea,
               const float* __restrict__ b1, const float* __restrict__ b2,
               const float* __restrict__ b3,
               const float* __restrict__ W4, const float* __restrict__ b4,
               float* __restrict__ out, int ntot)
{
    extern __shared__ char smem[];
    const uint32_t sbase = smem_u32(smem);
    const int tid = threadIdx.x, lane = tid & 31, wid = tid >> 5;
    const int m0 = (wid & 3) * 32, n0 = (wid >> 2) * 64;
    const int row0 = blockIdx.x * TILE_M;

    // biases + W4
    if (tid < HDIM) {
        ((float*)(smem + SM_BIAS))[tid]        = b1[tid];
        ((float*)(smem + SM_BIAS + 1024))[tid] = b2[tid];
        ((float*)(smem + SM_BIAS + 2048))[tid] = b3[tid];
        ((float*)(smem + SM_W4))[tid]          = W4[tid];
    }

    // e-tile: [m][k0..127] bf16 hi/lo (k>=100 zero)
    for (int i = 0; i < 32; i++) {
        int idx = tid + i * THREADS;       // 128*128 total
        int m = idx >> 7, k = idx & 127;
        int row = row0 + m;
        float v = (k < K1REAL && row < ntot) ? ea[(size_t)row * K1REAL + k] : 0.0f;
        __nv_bfloat16 hi = __float2bfloat16(v);
        __nv_bfloat16 lo = __float2bfloat16(v - __bfloat162float(hi));
        *(__nv_bfloat16*)(smem + SM_ACT_HI + m * ACT_STRIDE_B + k * 2) = hi;
        *(__nv_bfloat16*)(smem + SM_ACT_LO + m * ACT_STRIDE_B + k * 2) = lo;
    }

    const int ch_base[3] = {0, 4, 12};
    const int ch_cnt[3]  = {4, 8, 8};

    // ldmatrix lane addressing pieces
    const int midx = lane >> 3, l7 = lane & 7;
    const int a_roff = (midx & 1) * 8 + l7;          // A: row offset within m16
    const int a_koff = (midx >> 1) * 8;              // A: k offset within k16
    const int b_noff = (midx >> 1) * 8 + l7;         // B: n offset within n16
    const int b_koff = (midx & 1) * 8;               // B: k offset within k16

    for (int l = 0; l < 3; l++) {
        float acc[2][8][4];
#pragma unroll
        for (int mt = 0; mt < 2; mt++)
#pragma unroll
            for (int nt = 0; nt < 8; nt++)
#pragma unroll
                for (int q = 0; q < 4; q++) acc[mt][nt][q] = 0.0f;

        const int nch = ch_cnt[l];
        // stage chunk 0
        {
            const char* src = (const char*)WCH + (size_t)(ch_base[l]) * WCHUNK_B;
            uint32_t dst = sbase + SM_WBUF;
#pragma unroll
            for (int i = 0; i < 5; i++) {
                int off = (tid + i * THREADS) * 16;
                asm volatile("cp.async.cg.shared.global [%0], [%1], 16;"
                             :: "r"(dst + off), "l"(src + off));
            }
            asm volatile("cp.async.commit_group;");
        }

        for (int c = 0; c < nch; c++) {
            asm volatile("cp.async.wait_group 0;" ::: "memory");
            __syncthreads();   // chunk c visible; prior readers of other buf done
            if (c + 1 < nch) {
                const char* src = (const char*)WCH + (size_t)(ch_base[l] + c + 1) * WCHUNK_B;
                uint32_t dst = sbase + SM_WBUF + ((c + 1) & 1) * WCHUNK_B;
#pragma unroll
                for (int i = 0; i < 5; i++) {
                    int off = (tid + i * THREADS) * 16;
                    asm volatile("cp.async.cg.shared.global [%0], [%1], 16;"
                                 :: "r"(dst + off), "l"(src + off));
                }
                asm volatile("cp.async.commit_group;");
            }

            const uint32_t whi = sbase + SM_WBUF + (c & 1) * WCHUNK_B;
            const uint32_t wlo = whi + WIMG_B;
#pragma unroll
            for (int s = 0; s < 2; s++) {
                const int kg = c * KCH + s * 16;     // act k offset
                const int kw = s * 16;               // wbuf k offset
                uint32_t ah[2][4], al[2][4], bb[16];
#pragma unroll
                for (int mt = 0; mt < 2; mt++) {
                    uint32_t arow = (uint32_t)(m0 + mt * 16 + a_roff);
                    uint32_t aoff = arow * ACT_STRIDE_B + (uint32_t)(kg + a_koff) * 2;
                    ldsm_x4(ah[mt], sbase + SM_ACT_HI + aoff);
                    ldsm_x4(al[mt], sbase + SM_ACT_LO + aoff);
                }
                // B hi
#pragma unroll
                for (int ng = 0; ng < 4; ng++) {
                    uint32_t brow = (uint32_t)(n0 + ng * 16 + b_noff);
                    ldsm_x4(bb + ng * 4, whi + brow * WROW_B + (uint32_t)(kw + b_koff) * 2);
                }
#pragma unroll
                for (int nt = 0; nt < 8; nt++) {
                    uint32_t bx = bb[(nt >> 1) * 4 + (nt & 1) * 2];
                    uint32_t by = bb[(nt >> 1) * 4 + (nt & 1) * 2 + 1];
                    mma_bf16(acc[0][nt], ah[0], bx, by);
                    mma_bf16(acc[1][nt], ah[1], bx, by);
                    mma_bf16(acc[0][nt], al[0], bx, by);
                    mma_bf16(acc[1][nt], al[1], bx, by);
                }
                // B lo (x_hi * w_lo)
#pragma unroll
                for (int ng = 0; ng < 4; ng++) {
                    uint32_t brow = (uint32_t)(n0 + ng * 16 + b_noff);
                    ldsm_x4(bb + ng * 4, wlo + brow * WROW_B + (uint32_t)(kw + b_koff) * 2);
                }
#pragma unroll
                for (int nt = 0; nt < 8; nt++) {
                    uint32_t bx = bb[(nt >> 1) * 4 + (nt & 1) * 2];
                    uint32_t by = bb[(nt >> 1) * 4 + (nt & 1) * 2 + 1];
                    mma_bf16(acc[0][nt], ah[0], bx, by);
                    mma_bf16(acc[1][nt], ah[1], bx, by);
                }
            }
        }
        __syncthreads();   // all act reads done before in-place overwrite

        // epilogue: bias + tanh + hi/lo split, write act in place
        const float* bl = (const float*)(smem + SM_BIAS) + l * 256;
        const int r = lane >> 2, cp2 = (lane & 3) * 2;
#pragma unroll
        for (int mt = 0; mt < 2; mt++)
#pragma unroll
            for (int nt = 0; nt < 8; nt++) {
                int n = n0 + nt * 8 + cp2;
                float bn0 = bl[n], bn1 = bl[n + 1];
#pragma unroll
                for (int dp = 0; dp < 2; dp++) {
                    int m = m0 + mt * 16 + r + dp * 8;
                    float t0 = tanh_fast(acc[mt][nt][dp * 2]     + bn0);
                    float t1 = tanh_fast(acc[mt][nt][dp * 2 + 1] + bn1);
                    float h0 = __bfloat162float(__float2bfloat16(t0));
                    float h1 = __bfloat162float(__float2bfloat16(t1));
                    uint32_t off = (uint32_t)m * ACT_STRIDE_B + (uint32_t)n * 2;
                    *(uint32_t*)(smem + SM_ACT_HI + off) = pack_bf2(t0, t1);
                    *(uint32_t*)(smem + SM_ACT_LO + off) = pack_bf2(t0 - h0, t1 - h1);
                }
            }
        // next layer's first __syncthreads orders these writes before reads
    }
    __syncthreads();

    // layer 4: out[m] = sigmoid( sum_k act[m][k] * W4[k] + b4 ), 4 thr/row
    {
        int m = tid >> 2, seg = tid & 3;
        const float* w4 = (const float*)(smem + SM_W4) + seg * 64;
        const char* ph = smem + SM_ACT_HI + (uint32_t)m * ACT_STRIDE_B + seg * 128;
        const char* pl = smem + SM_ACT_LO + (uint32_t)m * ACT_STRIDE_B + seg * 128;
        float s = 0.f;
#pragma unroll
        for (int q = 0; q < 32; q++) {
            __nv_bfloat162 h2 = *(const __nv_bfloat162*)(ph + q * 4);
            __nv_bfloat162 l2 = *(const __nv_bfloat162*)(pl + q * 4);
            float a0 = __bfloat162float(h2.x) + __bfloat162float(l2.x);
            float a1 = __bfloat162float(h2.y) + __bfloat162float(l2.y);
            s += a0 * w4[q * 2] + a1 * w4[q * 2 + 1];
        }
        s += __shfl_down_sync(0xffffffff, s, 2);
        s += __shfl_down_sync(0xffffffff, s, 1);
        if (seg == 0) {
            float z = s + b4[0];
            int row = row0 + m;
            if (row < ntot) out[row] = 1.0f / (1.0f + expf(-z));
        }
    }
}

extern "C" void kernel_launch(void* const* d_in, const int* in_sizes, int n_in,
                              void* d_out, int out_size)
{
    // Inputs: x, edge_index, edge_attr, W1, b1, W2, b2, W3, b3, W4, b4
    const float* ea = (const float*)d_in[2];
    const float* W1 = (const float*)d_in[3];
    const float* b1 = (const float*)d_in[4];
    const float* W2 = (const float*)d_in[5];
    const float* b2 = (const float*)d_in[6];
    const float* W3 = (const float*)d_in[7];
    const float* b3 = (const float*)d_in[8];
    const float* W4 = (const float*)d_in[9];
    const float* b4 = (const float*)d_in[10];
    float* out = (float*)d_out;

    int ntot = out_size;                              // 500000
    int grid = (ntot + TILE_M - 1) / TILE_M;          // 3907

    wsplit_kernel<<<640, 256>>>(W1, W2, W3);

    cudaFuncSetAttribute(gnn_mma_kernel,
                         cudaFuncAttributeMaxDynamicSharedMemorySize, SMEM_TOTAL);
    gnn_mma_kernel<<<grid, THREADS, SMEM_TOTAL>>>(ea, b1, b2, b3, W4, b4, out, ntot);
}